// round 6
// baseline (speedup 1.0000x reference)
#include <cuda_runtime.h>
#include <cstdint>

// x:      (16, 16, 64, 512)  f32
// kernel: (32, 16, 4)        f32
// points: (16, 3, 64, 512)   f32
// out:    (16, 32, 62, 510)  f32
#define CH_STRIDE 32768
#define HP 62
#define WP 510
#define OUT_PLANE (62*510)
#define CSTR 68               // padded smem row stride in words (conflict-free)

typedef unsigned long long u64;
typedef unsigned int u32;

__device__ __forceinline__ u64 pk(float lo, float hi) {
    u64 r; asm("mov.b64 %0, {%1,%2};" : "=l"(r) : "f"(lo), "f"(hi)); return r;
}
__device__ __forceinline__ void upk(u64 v, float& lo, float& hi) {
    asm("mov.b64 {%0,%1}, %2;" : "=f"(lo), "=f"(hi) : "l"(v));
}
__device__ __forceinline__ u64 fma2(u64 a, u64 b, u64 c) {
    u64 d; asm("fma.rn.f32x2 %0, %1, %2, %3;" : "=l"(d) : "l"(a), "l"(b), "l"(c)); return d;
}
__device__ __forceinline__ u64 add2(u64 a, u64 b) {
    u64 d; asm("add.rn.f32x2 %0, %1, %2;" : "=l"(d) : "l"(a), "l"(b)); return d;
}
__device__ __forceinline__ u64 mul2(u64 a, u64 b) {
    u64 d; asm("mul.rn.f32x2 %0, %1, %2;" : "=l"(d) : "l"(a), "l"(b)); return d;
}
__device__ __forceinline__ u64 neg2(u64 a) { return a ^ 0x8000000080000000ULL; }

__device__ __forceinline__ u32 tf32r(float f) {
    u32 r; asm("cvt.rna.tf32.f32 %0, %1;" : "=r"(r) : "f"(f)); return r;
}

__device__ __forceinline__ void mma_tf32(float& d0, float& d1, float& d2, float& d3,
                                         u32 a0, u32 a1, u32 a2, u32 a3,
                                         u32 b0, u32 b1) {
    asm volatile("mma.sync.aligned.m16n8k8.row.col.f32.tf32.tf32.f32 "
                 "{%0,%1,%2,%3}, {%4,%5,%6,%7}, {%8,%9}, {%0,%1,%2,%3};"
                 : "+f"(d0), "+f"(d1), "+f"(d2), "+f"(d3)
                 : "r"(a0), "r"(a1), "r"(a2), "r"(a3), "r"(b0), "r"(b1));
}

// Dynamic smem: C tile [256 px][CSTR]  then  K [32 o][CSTR]
#define SMEM_WORDS ((256 + 32) * CSTR)

extern __shared__ u32 smw[];

__global__ void __launch_bounds__(128, 2)
flex_conv_mma_kernel(const float* __restrict__ x,
                     const float* __restrict__ kern,
                     const float* __restrict__ pts,
                     float* __restrict__ out)
{
    u32* Cs  = smw;
    u32* Ksm = smw + 256 * CSTR;

    const int tid  = threadIdx.x;
    const int lane = tid & 31;

    // Stage K -> smem as tf32: Ksm[o][c], c = i*4+d
    #pragma unroll
    for (int t = 0; t < 16; ++t) {
        int idx = t * 128 + tid;        // = o*64 + c
        int o = idx >> 6, c = idx & 63;
        Ksm[o * CSTR + c] = tf32r(kern[idx]);
    }

    // ---------------- phase 1: box sums -> C (2 px per thread) ----------------
    const int w  = blockIdx.x * 128 + tid;       // 0..511 (lanes >=510 are pad)
    const int wl = (w < WP - 1) ? w : (WP - 1);  // clamp loads in-bounds
    const int h0 = blockIdx.y * 2;
    const int b  = blockIdx.z;

    const float* pb = pts + ((size_t)(b * 3) * 64 + h0) * 512 + wl;
    u64 pp[4][3][3];
    #pragma unroll
    for (int d = 0; d < 3; ++d)
        #pragma unroll
        for (int r = 0; r < 4; ++r)
            #pragma unroll
            for (int f = 0; f < 3; ++f) {
                float v = pb[d * CH_STRIDE + r * 512 + f];
                pp[r][f][d] = pk(v, v);
            }

    const float* xb = x + ((size_t)(b * 16) * 64 + h0) * 512 + wl;
    // px0 = tid (row h0), px1 = 128+tid (row h0+1)
    u32* c0p = Cs + tid * CSTR;
    u32* c1p = Cs + (128 + tid) * CSTR;

    #pragma unroll 1
    for (int pr = 0; pr < 8; ++pr) {
        const float* xc0 = xb + (size_t)(2 * pr) * CH_STRIDE;
        const float* xc1 = xc0 + CH_STRIDE;

        u64 xx[4][3];
        #pragma unroll
        for (int r = 0; r < 4; ++r)
            #pragma unroll
            for (int f = 0; f < 3; ++f)
                xx[r][f] = pk(xc0[r * 512 + f], xc1[r * 512 + f]);

        u64 Rx[4], Rb[3][4];
        #pragma unroll
        for (int r = 0; r < 4; ++r) {
            Rx[r] = add2(add2(xx[r][0], xx[r][1]), xx[r][2]);
            #pragma unroll
            for (int d = 0; d < 3; ++d)
                Rb[d][r] = fma2(pp[r][2][d], xx[r][2],
                            fma2(pp[r][1][d], xx[r][1],
                             mul2(pp[r][0][d], xx[r][0])));
        }

        u64 A0 = add2(add2(Rx[0], Rx[1]), Rx[2]);
        u64 A1 = add2(add2(Rx[1], Rx[2]), Rx[3]);
        u64 C0[3], C1[3];
        #pragma unroll
        for (int d = 0; d < 3; ++d) {
            u64 B0 = add2(add2(Rb[d][0], Rb[d][1]), Rb[d][2]);
            u64 B1 = add2(add2(Rb[d][1], Rb[d][2]), Rb[d][3]);
            C0[d] = fma2(pp[1][1][d], A0, neg2(B0));
            C1[d] = fma2(pp[2][1][d], A1, neg2(B1));
        }

        // C columns for this pr: 8pr..8pr+7 = [C(2pr,d),A(2pr),C(2pr+1,d),A(2pr+1)]
        float cl[3], ch[3], al, ah, dl[3], dh[3], bl, bh;
        upk(A0, al, ah); upk(A1, bl, bh);
        #pragma unroll
        for (int d = 0; d < 3; ++d) { upk(C0[d], cl[d], ch[d]); upk(C1[d], dl[d], dh[d]); }

        uint4 s0a = make_uint4(tf32r(cl[0]), tf32r(cl[1]), tf32r(cl[2]), tf32r(al));
        uint4 s0b = make_uint4(tf32r(ch[0]), tf32r(ch[1]), tf32r(ch[2]), tf32r(ah));
        uint4 s1a = make_uint4(tf32r(dl[0]), tf32r(dl[1]), tf32r(dl[2]), tf32r(bl));
        uint4 s1b = make_uint4(tf32r(dh[0]), tf32r(dh[1]), tf32r(dh[2]), tf32r(bh));
        *reinterpret_cast<uint4*>(c0p + 8 * pr)     = s0a;
        *reinterpret_cast<uint4*>(c0p + 8 * pr + 4) = s0b;
        *reinterpret_cast<uint4*>(c1p + 8 * pr)     = s1a;
        *reinterpret_cast<uint4*>(c1p + 8 * pr + 4) = s1b;
    }
    __syncthreads();

    // ---------------- phase 2: out[256px,32o] = C[256x64] * K^T via mma ----------------
    const int g  = lane >> 2;     // 0..7
    const int cq = lane & 3;      // 0..3

    // B fragments (weights), resident in registers: bf[nt][kt][2]
    u32 bf[4][8][2];
    #pragma unroll
    for (int nt = 0; nt < 4; ++nt)
        #pragma unroll
        for (int kt = 0; kt < 8; ++kt) {
            const u32* kp = Ksm + (nt * 8 + g) * CSTR + kt * 8 + cq;
            bf[nt][kt][0] = kp[0];
            bf[nt][kt][1] = kp[4];
        }

    float dd[4][4][4];
    #pragma unroll
    for (int mt = 0; mt < 4; ++mt)
        #pragma unroll
        for (int nt = 0; nt < 4; ++nt)
            #pragma unroll
            for (int e = 0; e < 4; ++e) dd[mt][nt][e] = 0.0f;

    const int pxb = (tid >> 5) * 64;   // warp's 64-px slab

    #pragma unroll
    for (int kt = 0; kt < 8; ++kt) {
        u32 af[4][4];
        #pragma unroll
        for (int mt = 0; mt < 4; ++mt) {
            const u32* ap = Cs + (pxb + mt * 16 + g) * CSTR + kt * 8 + cq;
            af[mt][0] = ap[0];
            af[mt][1] = ap[8 * CSTR];
            af[mt][2] = ap[4];
            af[mt][3] = ap[8 * CSTR + 4];
        }
        #pragma unroll
        for (int mt = 0; mt < 4; ++mt)
            #pragma unroll
            for (int nt = 0; nt < 4; ++nt)
                mma_tf32(dd[mt][nt][0], dd[mt][nt][1], dd[mt][nt][2], dd[mt][nt][3],
                         af[mt][0], af[mt][1], af[mt][2], af[mt][3],
                         bf[nt][kt][0], bf[nt][kt][1]);
    }

    // ---------------- epilogue ----------------
    const int wq  = tid >> 5;
    const int hl  = wq >> 1;              // warp's h offset (0/1)
    const int wl0 = (wq & 1) * 64;        // warp's w-local base
    const int h   = h0 + hl;
    float* ob = out + (size_t)(b * 32) * OUT_PLANE + (size_t)h * WP;

    #pragma unroll
    for (int mt = 0; mt < 4; ++mt) {
        const int wla = wl0 + mt * 16 + g;
        const int wA = blockIdx.x * 128 + wla;
        const int wB = wA + 8;
        const bool mA = (wA < WP), mB = (wB < WP);
        #pragma unroll
        for (int nt = 0; nt < 4; ++nt) {
            const int o = nt * 8 + 2 * cq;
            float* p = ob + (size_t)o * OUT_PLANE;
            if (mA) { p[wA] = dd[mt][nt][0]; p[OUT_PLANE + wA] = dd[mt][nt][1]; }
            if (mB) { p[wB] = dd[mt][nt][2]; p[OUT_PLANE + wB] = dd[mt][nt][3]; }
        }
    }
}

extern "C" void kernel_launch(void* const* d_in, const int* in_sizes, int n_in,
                              void* d_out, int out_size)
{
    const float* x = nullptr; const float* kern = nullptr; const float* pts = nullptr;
    for (int i = 0; i < n_in; ++i) {
        if (in_sizes[i] == 8388608)      x    = (const float*)d_in[i];
        else if (in_sizes[i] == 2048)    kern = (const float*)d_in[i];
        else if (in_sizes[i] == 1572864) pts  = (const float*)d_in[i];
    }
    const int smem_bytes = SMEM_WORDS * 4;   // 78336 B
    cudaFuncSetAttribute(flex_conv_mma_kernel,
                         cudaFuncAttributeMaxDynamicSharedMemorySize, smem_bytes);
    dim3 grid(4, 31, 16);   // 4 w-tiles of 128, 31 h-pairs, batch
    flex_conv_mma_kernel<<<grid, 128, smem_bytes>>>(x, kern, pts, (float*)d_out);
}

// round 8
// speedup vs baseline: 1.8172x; 1.8172x over previous
#include <cuda_runtime.h>
#include <cstdint>

// x:      (16, 16, 64, 512)  f32
// kernel: (32, 16, 4)        f32
// points: (16, 3, 64, 512)   f32
// out:    (16, 32, 62, 510)  f32
#define CH_STRIDE 32768
#define HP 62
#define WP 510
#define OUT_PLANE (62*510)
#define KSTR 68                 // padded K smem stride (words)

typedef unsigned long long u64;
typedef unsigned int u32;

__device__ __forceinline__ u64 pk(float lo, float hi) {
    u64 r; asm("mov.b64 %0, {%1,%2};" : "=l"(r) : "f"(lo), "f"(hi)); return r;
}
__device__ __forceinline__ void upk(u64 v, float& lo, float& hi) {
    asm("mov.b64 {%0,%1}, %2;" : "=f"(lo), "=f"(hi) : "l"(v));
}
__device__ __forceinline__ u64 fma2(u64 a, u64 b, u64 c) {
    u64 d; asm("fma.rn.f32x2 %0, %1, %2, %3;" : "=l"(d) : "l"(a), "l"(b), "l"(c)); return d;
}
__device__ __forceinline__ u64 add2(u64 a, u64 b) {
    u64 d; asm("add.rn.f32x2 %0, %1, %2;" : "=l"(d) : "l"(a), "l"(b)); return d;
}
__device__ __forceinline__ u64 neg2(u64 a) { return a ^ 0x8000000080000000ULL; }

__device__ __forceinline__ u32 tf32r(float f) {
    u32 r; asm("cvt.rna.tf32.f32 %0, %1;" : "=r"(r) : "f"(f)); return r;
}

__device__ __forceinline__ void mma_tf32(float& d0, float& d1, float& d2, float& d3,
                                         u32 a0, u32 a1, u32 a2, u32 a3,
                                         u32 b0, u32 b1) {
    asm volatile("mma.sync.aligned.m16n8k8.row.col.f32.tf32.tf32.f32 "
                 "{%0,%1,%2,%3}, {%4,%5,%6,%7}, {%8,%9}, {%0,%1,%2,%3};"
                 : "+f"(d0), "+f"(d1), "+f"(d2), "+f"(d3)
                 : "r"(a0), "r"(a1), "r"(a2), "r"(a3), "r"(b0), "r"(b1));
}

__global__ void __launch_bounds__(128, 5)
flex_conv_mma5_kernel(const float* __restrict__ x,
                      const float* __restrict__ kern,
                      const float* __restrict__ pts,
                      float* __restrict__ out)
{
    // C tile: 128 px rows x 64 words, XOR-swizzled in 4-word groups (no pad).
    __shared__ u32 Cs[128 * 64];        // 32 KB
    __shared__ u32 Ksm[32 * KSTR];      // 8.7 KB

    const int tid = threadIdx.x;

    // Stage weights: Ksm[o][c] tf32, c = i*4+d
    #pragma unroll
    for (int t = 0; t < 16; ++t) {
        int idx = t * 128 + tid;        // o*64 + c
        int o = idx >> 6, c = idx & 63;
        Ksm[o * KSTR + c] = tf32r(kern[idx]);
    }

    const int w  = blockIdx.x * 128 + tid;
    const int wl = (w < WP - 1) ? w : (WP - 1);   // clamp; pad lanes masked at store
    const int h  = blockIdx.y;
    const int b  = blockIdx.z;

    const float* xb = x   + ((size_t)(b * 16) * 64 + h) * 512 + wl;
    const float* pb = pts + ((size_t)(b * 3)  * 64 + h) * 512 + wl;

    // Window center: points[b, d, h+1, w+1]
    const float t0 = pb[512 + 1];
    const float t1 = pb[CH_STRIDE + 512 + 1];
    const float t2 = pb[2 * CH_STRIDE + 512 + 1];
    const u64 ctr0 = pk(t0, t0), ctr1 = pk(t1, t1), ctr2 = pk(t2, t2);

    // ---------------- phase 1: box sums in two channel-half passes ----------------
    #pragma unroll 1
    for (int half = 0; half < 2; ++half) {
        u64 A2[4], Bn[3][4];
        #pragma unroll
        for (int j = 0; j < 4; ++j) { A2[j] = 0ull; Bn[0][j] = 0ull; Bn[1][j] = 0ull; Bn[2][j] = 0ull; }

        #pragma unroll
        for (int r = 0; r < 3; ++r) {
            #pragma unroll
            for (int f = 0; f < 3; ++f) {
                const int off = r * 512 + f;
                float p0 = pb[off];
                float p1 = pb[CH_STRIDE + off];
                float p2 = pb[2 * CH_STRIDE + off];
                u64 q0 = pk(p0, p0), q1 = pk(p1, p1), q2 = pk(p2, p2);
                #pragma unroll
                for (int j = 0; j < 4; ++j) {
                    const int ch = half * 8 + 2 * j;
                    u64 xx = pk(xb[(size_t)ch * CH_STRIDE + off],
                                xb[(size_t)(ch + 1) * CH_STRIDE + off]);
                    A2[j]    = add2(A2[j], xx);
                    Bn[0][j] = fma2(q0, xx, Bn[0][j]);
                    Bn[1][j] = fma2(q1, xx, Bn[1][j]);
                    Bn[2][j] = fma2(q2, xx, Bn[2][j]);
                }
            }
        }

        // Combine + write C columns for channels of this half
        #pragma unroll
        for (int j = 0; j < 4; ++j) {
            const int pr = half * 4 + j;          // channel pair index
            u64 C0 = fma2(ctr0, A2[j], neg2(Bn[0][j]));
            u64 C1 = fma2(ctr1, A2[j], neg2(Bn[1][j]));
            u64 C2 = fma2(ctr2, A2[j], neg2(Bn[2][j]));
            float c0l, c0h, c1l, c1h, c2l, c2h, al, ah;
            upk(C0, c0l, c0h); upk(C1, c1l, c1h); upk(C2, c2l, c2h); upk(A2[j], al, ah);

            // cols 8pr..8pr+3 = channel 2pr (lo), 8pr+4..+7 = channel 2pr+1 (hi)
            const int base = tid * 64;
            const int sw   = tid & 15;
            u32* p0 = Cs + base + (((2 * pr)     ^ sw) << 2);
            u32* p1 = Cs + base + (((2 * pr + 1) ^ sw) << 2);
            *reinterpret_cast<uint4*>(p0) =
                make_uint4(tf32r(c0l), tf32r(c1l), tf32r(c2l), tf32r(al));
            *reinterpret_cast<uint4*>(p1) =
                make_uint4(tf32r(c0h), tf32r(c1h), tf32r(c2h), tf32r(ah));
        }
    }
    __syncthreads();

    // ---------------- phase 2: out[128px, 32o] = C[128x64] * K^T ----------------
    const int lane = tid & 31;
    const int wq   = tid >> 5;
    const int g    = lane >> 2;
    const int cq   = lane & 3;
    const int rbase = wq * 32;          // warp's 32-px slab

    float dd[2][4][4];
    #pragma unroll
    for (int mt = 0; mt < 2; ++mt)
        #pragma unroll
        for (int nt = 0; nt < 4; ++nt)
            #pragma unroll
            for (int e = 0; e < 4; ++e) dd[mt][nt][e] = 0.0f;

    #pragma unroll
    for (int kt = 0; kt < 8; ++kt) {
        u32 bf[4][2];
        #pragma unroll
        for (int nt = 0; nt < 4; ++nt) {
            const u32* kp = Ksm + (nt * 8 + g) * KSTR + kt * 8 + cq;
            bf[nt][0] = kp[0];
            bf[nt][1] = kp[4];
        }
        #pragma unroll
        for (int mt = 0; mt < 2; ++mt) {
            const int r0 = rbase + mt * 16 + g;   // r0 & 15 == g
            const int r1 = r0 + 8;                // r1 & 15 == g + 8
            u32 a0 = Cs[r0 * 64 + (((2 * kt)     ^ g)       << 2) + cq];
            u32 a1 = Cs[r1 * 64 + (((2 * kt)     ^ (g + 8)) << 2) + cq];
            u32 a2 = Cs[r0 * 64 + (((2 * kt + 1) ^ g)       << 2) + cq];
            u32 a3 = Cs[r1 * 64 + (((2 * kt + 1) ^ (g + 8)) << 2) + cq];
            #pragma unroll
            for (int nt = 0; nt < 4; ++nt)
                mma_tf32(dd[mt][nt][0], dd[mt][nt][1], dd[mt][nt][2], dd[mt][nt][3],
                         a0, a1, a2, a3, bf[nt][0], bf[nt][1]);
        }
    }

    // ---------------- epilogue ----------------
    float* ob = out + (size_t)(b * 32) * OUT_PLANE + (size_t)h * WP;
    const int wA0 = blockIdx.x * 128 + rbase;
    #pragma unroll
    for (int mt = 0; mt < 2; ++mt) {
        const int wA = wA0 + mt * 16 + g;
        const int wB = wA + 8;
        const bool mA = (wA < WP), mB = (wB < WP);
        #pragma unroll
        for (int nt = 0; nt < 4; ++nt) {
            const int o = nt * 8 + 2 * cq;
            float* p = ob + (size_t)o * OUT_PLANE;
            if (mA) { p[wA] = dd[mt][nt][0]; p[OUT_PLANE + wA] = dd[mt][nt][1]; }
            if (mB) { p[wB] = dd[mt][nt][2]; p[OUT_PLANE + wB] = dd[mt][nt][3]; }
        }
    }
}

extern "C" void kernel_launch(void* const* d_in, const int* in_sizes, int n_in,
                              void* d_out, int out_size)
{
    const float* x = nullptr; const float* kern = nullptr; const float* pts = nullptr;
    for (int i = 0; i < n_in; ++i) {
        if (in_sizes[i] == 8388608)      x    = (const float*)d_in[i];
        else if (in_sizes[i] == 2048)    kern = (const float*)d_in[i];
        else if (in_sizes[i] == 1572864) pts  = (const float*)d_in[i];
    }
    dim3 grid(4, 62, 16);   // 4 w-tiles of 128, 62 h rows, batch
    flex_conv_mma5_kernel<<<grid, 128>>>(x, kern, pts, (float*)d_out);
}